// round 2
// baseline (speedup 1.0000x reference)
#include <cuda_runtime.h>
#include <cstdint>

#define NODES 100000
#define FDIM  128
#define NCLS  40

// Scratch (allocation-free rule: __device__ globals)
__device__ float g_agg[(size_t)NODES * FDIM];
__device__ float g_x1 [(size_t)NODES * FDIM];
__device__ float g_x2 [(size_t)NODES * FDIM];

// ---------------------------------------------------------------------------
// Scatter: agg[dst] += x[src], one warp per edge, 4 floats per lane via
// vectorized red.global.add.v4.f32 (no return path, L2-side reduction).
// ---------------------------------------------------------------------------
__global__ void __launch_bounds__(256) scatter_kernel(
    const float* __restrict__ x,
    const int* __restrict__ src, const int* __restrict__ dst,
    float* __restrict__ agg, int E)
{
    int w    = (blockIdx.x * blockDim.x + threadIdx.x) >> 5;
    int lane = threadIdx.x & 31;
    if (w >= E) return;
    int s = __ldg(src + w);
    int d = __ldg(dst + w);
    float4 v = *reinterpret_cast<const float4*>(x + (size_t)s * FDIM + lane * 4);
    float* p = agg + (size_t)d * FDIM + lane * 4;
    asm volatile("red.global.add.v4.f32 [%0], {%1,%2,%3,%4};"
                 :: "l"(p), "f"(v.x), "f"(v.y), "f"(v.z), "f"(v.w) : "memory");
}

// ---------------------------------------------------------------------------
// Fused GraphConv: out = relu(agg @ W_rel + xin @ W_root + b)
// Block: 64 nodes x 128 feats, 256 threads, thread = 8 nodes x 4 feats.
// k-tiles of 32; weights + activations staged in smem (48KB).
// ---------------------------------------------------------------------------
__global__ void __launch_bounds__(256) conv_kernel(
    const float* __restrict__ xin, const float* __restrict__ agg,
    const float* __restrict__ Wrel, const float* __restrict__ Wroot,
    const float* __restrict__ bias, float* __restrict__ out)
{
    __shared__ float sWr[32][128];
    __shared__ float sWo[32][128];
    __shared__ float sX [64][32];
    __shared__ float sA [64][32];

    int tid = threadIdx.x;
    int tx  = tid & 31;       // feature group (4 feats)
    int ty  = tid >> 5;       // node group (8 nodes)
    int f0  = tx * 4;
    int nodeBase = blockIdx.x * 64;

    float4 bv = *reinterpret_cast<const float4*>(bias + f0);
    float acc[8][4];
    #pragma unroll
    for (int n = 0; n < 8; n++) {
        acc[n][0] = bv.x; acc[n][1] = bv.y; acc[n][2] = bv.z; acc[n][3] = bv.w;
    }

    for (int kt = 0; kt < FDIM; kt += 32) {
        // Load W tiles: 32x128 each, float4 per thread x4
        #pragma unroll
        for (int i = tid; i < 1024; i += 256) {
            int kk = i >> 5;
            int fq = (i & 31) * 4;
            *reinterpret_cast<float4*>(&sWr[kk][fq]) =
                *reinterpret_cast<const float4*>(Wrel + (size_t)(kt + kk) * FDIM + fq);
            *reinterpret_cast<float4*>(&sWo[kk][fq]) =
                *reinterpret_cast<const float4*>(Wroot + (size_t)(kt + kk) * FDIM + fq);
        }
        // Load activation tiles: 64 nodes x 32 k
        #pragma unroll
        for (int i = tid; i < 512; i += 256) {
            int n  = i >> 3;
            int kq = (i & 7) * 4;
            int node = nodeBase + n;
            float4 xv = make_float4(0.f, 0.f, 0.f, 0.f);
            float4 av = xv;
            if (node < NODES) {
                xv = *reinterpret_cast<const float4*>(xin + (size_t)node * FDIM + kt + kq);
                av = *reinterpret_cast<const float4*>(agg + (size_t)node * FDIM + kt + kq);
            }
            *reinterpret_cast<float4*>(&sX[n][kq]) = xv;
            *reinterpret_cast<float4*>(&sA[n][kq]) = av;
        }
        __syncthreads();

        #pragma unroll 8
        for (int kk = 0; kk < 32; kk++) {
            float4 wr = *reinterpret_cast<const float4*>(&sWr[kk][f0]);
            float4 wo = *reinterpret_cast<const float4*>(&sWo[kk][f0]);
            #pragma unroll
            for (int n = 0; n < 8; n++) {
                float xv = sX[ty * 8 + n][kk];   // warp-broadcast
                float av = sA[ty * 8 + n][kk];
                acc[n][0] = fmaf(av, wr.x, fmaf(xv, wo.x, acc[n][0]));
                acc[n][1] = fmaf(av, wr.y, fmaf(xv, wo.y, acc[n][1]));
                acc[n][2] = fmaf(av, wr.z, fmaf(xv, wo.z, acc[n][2]));
                acc[n][3] = fmaf(av, wr.w, fmaf(xv, wo.w, acc[n][3]));
            }
        }
        __syncthreads();
    }

    #pragma unroll
    for (int n = 0; n < 8; n++) {
        int node = nodeBase + ty * 8 + n;
        if (node < NODES) {
            float4 o;
            o.x = fmaxf(acc[n][0], 0.f);
            o.y = fmaxf(acc[n][1], 0.f);
            o.z = fmaxf(acc[n][2], 0.f);
            o.w = fmaxf(acc[n][3], 0.f);
            *reinterpret_cast<float4*>(out + (size_t)node * FDIM + f0) = o;
        }
    }
}

// ---------------------------------------------------------------------------
// Classifier: out = log_softmax([x1|x2] @ W_lin + b_lin)
// Warp per node, W_lin (256x40) in smem, h row staged in smem per warp.
// Lane c holds class c; lanes 0..7 additionally hold classes 32..39.
// ---------------------------------------------------------------------------
__global__ void __launch_bounds__(128) cls_kernel(
    const float* __restrict__ x1, const float* __restrict__ x2,
    const float* __restrict__ Wlin, const float* __restrict__ blin,
    float* __restrict__ out, int nWarpsTotal)
{
    __shared__ float sW[2 * FDIM * NCLS];   // 256*40 = 40KB
    __shared__ float sb[NCLS];
    __shared__ float sH[4][2 * FDIM];

    int tid = threadIdx.x;
    for (int i = tid; i < 2 * FDIM * NCLS; i += 128) sW[i] = Wlin[i];
    if (tid < NCLS) sb[tid] = blin[tid];
    __syncthreads();

    int wid  = tid >> 5;
    int lane = tid & 31;
    int gw   = blockIdx.x * 4 + wid;
    float* h = sH[wid];

    for (int node = gw; node < NODES; node += nWarpsTotal) {
        // stage h = [x1 row | x2 row]
        const float4* p1 = reinterpret_cast<const float4*>(x1 + (size_t)node * FDIM);
        const float4* p2 = reinterpret_cast<const float4*>(x2 + (size_t)node * FDIM);
        reinterpret_cast<float4*>(h)[lane]      = p1[lane];
        reinterpret_cast<float4*>(h)[32 + lane] = p2[lane];
        __syncwarp();

        float v0 = sb[lane];
        float v1 = (lane < 8) ? sb[32 + lane] : 0.f;
        #pragma unroll 8
        for (int k = 0; k < 2 * FDIM; k++) {
            float hv = h[k];
            v0 = fmaf(hv, sW[k * NCLS + lane], v0);
            if (lane < 8) v1 = fmaf(hv, sW[k * NCLS + 32 + lane], v1);
        }

        float m = (lane < 8) ? fmaxf(v0, v1) : v0;
        #pragma unroll
        for (int off = 16; off; off >>= 1)
            m = fmaxf(m, __shfl_xor_sync(0xffffffffu, m, off));
        float s = expf(v0 - m) + ((lane < 8) ? expf(v1 - m) : 0.f);
        #pragma unroll
        for (int off = 16; off; off >>= 1)
            s += __shfl_xor_sync(0xffffffffu, s, off);
        float lse = m + logf(s);

        out[(size_t)node * NCLS + lane] = v0 - lse;
        if (lane < 8) out[(size_t)node * NCLS + 32 + lane] = v1 - lse;
        __syncwarp();
    }
}

// ---------------------------------------------------------------------------
extern "C" void kernel_launch(void* const* d_in, const int* in_sizes, int n_in,
                              void* d_out, int out_size)
{
    const float* x      = (const float*)d_in[0];
    const int*   eidx   = (const int*)  d_in[1];
    const float* Wrel1  = (const float*)d_in[2];
    const float* b1     = (const float*)d_in[3];
    const float* Wroot1 = (const float*)d_in[4];
    const float* Wrel2  = (const float*)d_in[5];
    const float* b2     = (const float*)d_in[6];
    const float* Wroot2 = (const float*)d_in[7];
    const float* Wlin   = (const float*)d_in[8];
    const float* blin   = (const float*)d_in[9];
    float* out = (float*)d_out;

    int E = in_sizes[1] / 2;
    const int* src = eidx;
    const int* dst = eidx + E;

    float *agg, *x1, *x2;
    cudaGetSymbolAddress((void**)&agg, g_agg);
    cudaGetSymbolAddress((void**)&x1,  g_x1);
    cudaGetSymbolAddress((void**)&x2,  g_x2);

    size_t featBytes = (size_t)NODES * FDIM * sizeof(float);
    int sblocks = (E + 7) / 8;            // 8 warps (edges) per block
    int cblocks = (NODES + 63) / 64;

    // Layer 1
    cudaMemsetAsync(agg, 0, featBytes, 0);
    scatter_kernel<<<sblocks, 256>>>(x, src, dst, agg, E);
    conv_kernel<<<cblocks, 256>>>(x, agg, Wrel1, Wroot1, b1, x1);

    // Layer 2
    cudaMemsetAsync(agg, 0, featBytes, 0);
    scatter_kernel<<<sblocks, 256>>>(x1, src, dst, agg, E);
    conv_kernel<<<cblocks, 256>>>(x1, agg, Wrel2, Wroot2, b2, x2);

    // Classifier + log_softmax
    int clsBlocks = 592;                  // 4 warps/block -> 2368 warps
    cls_kernel<<<clsBlocks, 128>>>(x1, x2, Wlin, blin, out, clsBlocks * 4);
}

// round 3
// speedup vs baseline: 1.4483x; 1.4483x over previous
#include <cuda_runtime.h>
#include <cstdint>

#define NODES 100000
#define FDIM  128
#define NCLS  40
#define EMAX  1700000

// Scratch (allocation-free rule: __device__ globals)
__device__ float g_agg[(size_t)NODES * FDIM];
__device__ float g_x1 [(size_t)NODES * FDIM];
__device__ float g_x2 [(size_t)NODES * FDIM];
__device__ int   g_deg[NODES];
__device__ int   g_cursor[NODES];
__device__ int   g_off[NODES + 1];
__device__ int   g_csr[EMAX];

// ---------------------------------------------------------------------------
// CSR build: histogram of dst degrees
// ---------------------------------------------------------------------------
__global__ void __launch_bounds__(256) hist_kernel(
    const int* __restrict__ dst, int* __restrict__ deg, int E)
{
    int e = blockIdx.x * blockDim.x + threadIdx.x;
    if (e < E) atomicAdd(&deg[__ldg(dst + e)], 1);
}

// Single-block exclusive scan over NODES ints (1024 threads, chunked)
__global__ void __launch_bounds__(1024) scan_kernel(
    const int* __restrict__ deg, int* __restrict__ off, int n)
{
    __shared__ int wsum[32];
    __shared__ int blocktot;
    int tid = threadIdx.x, lane = tid & 31, wid = tid >> 5;
    int running = 0;

    for (int base = 0; base < n; base += 1024) {
        int idx = base + tid;
        int v = (idx < n) ? deg[idx] : 0;
        int s = v;
        #pragma unroll
        for (int o = 1; o < 32; o <<= 1) {
            int t = __shfl_up_sync(0xffffffffu, s, o);
            if (lane >= o) s += t;
        }
        if (lane == 31) wsum[wid] = s;
        __syncthreads();
        if (wid == 0) {
            int ws = wsum[lane];
            int ss = ws;
            #pragma unroll
            for (int o = 1; o < 32; o <<= 1) {
                int t = __shfl_up_sync(0xffffffffu, ss, o);
                if (lane >= o) ss += t;
            }
            if (lane == 31) blocktot = ss;
            wsum[lane] = ss - ws;   // exclusive warp offset
        }
        __syncthreads();
        int excl = running + wsum[wid] + (s - v);
        if (idx < n) off[idx] = excl;
        running += blocktot;
        __syncthreads();
    }
    if (tid == 0) off[n] = running;
}

__global__ void __launch_bounds__(256) fill_kernel(
    const int* __restrict__ src, const int* __restrict__ dst,
    const int* __restrict__ off, int* __restrict__ cursor,
    int* __restrict__ csr, int E)
{
    int e = blockIdx.x * blockDim.x + threadIdx.x;
    if (e >= E) return;
    int d = __ldg(dst + e);
    int pos = atomicAdd(&cursor[d], 1);
    csr[__ldg(off + d) + pos] = __ldg(src + e);
}

// ---------------------------------------------------------------------------
// Gather aggregation: agg[i] = sum_{j in N(i)} x[j]. Warp per node,
// float4 per lane, neighbors unrolled x2 for MLP. No atomics, no memset.
// ---------------------------------------------------------------------------
__global__ void __launch_bounds__(256) gather_kernel(
    const float* __restrict__ x,
    const int* __restrict__ off, const int* __restrict__ csr,
    float* __restrict__ agg)
{
    int node = (blockIdx.x * blockDim.x + threadIdx.x) >> 5;
    int lane = threadIdx.x & 31;
    if (node >= NODES) return;
    int lo = __ldg(off + node), hi = __ldg(off + node + 1);

    float4 a = make_float4(0.f, 0.f, 0.f, 0.f);
    int i = lo;
    for (; i + 1 < hi; i += 2) {
        int s0 = __ldg(csr + i);
        int s1 = __ldg(csr + i + 1);
        float4 v0 = *reinterpret_cast<const float4*>(x + (size_t)s0 * FDIM + lane * 4);
        float4 v1 = *reinterpret_cast<const float4*>(x + (size_t)s1 * FDIM + lane * 4);
        a.x += v0.x + v1.x; a.y += v0.y + v1.y;
        a.z += v0.z + v1.z; a.w += v0.w + v1.w;
    }
    if (i < hi) {
        int s0 = __ldg(csr + i);
        float4 v0 = *reinterpret_cast<const float4*>(x + (size_t)s0 * FDIM + lane * 4);
        a.x += v0.x; a.y += v0.y; a.z += v0.z; a.w += v0.w;
    }
    *reinterpret_cast<float4*>(agg + (size_t)node * FDIM + lane * 4) = a;
}

// ---------------------------------------------------------------------------
// Fused GraphConv: out = relu(agg @ W_rel + xin @ W_root + b)   (unchanged)
// ---------------------------------------------------------------------------
__global__ void __launch_bounds__(256) conv_kernel(
    const float* __restrict__ xin, const float* __restrict__ agg,
    const float* __restrict__ Wrel, const float* __restrict__ Wroot,
    const float* __restrict__ bias, float* __restrict__ out)
{
    __shared__ float sWr[32][128];
    __shared__ float sWo[32][128];
    __shared__ float sX [64][32];
    __shared__ float sA [64][32];

    int tid = threadIdx.x;
    int tx  = tid & 31;
    int ty  = tid >> 5;
    int f0  = tx * 4;
    int nodeBase = blockIdx.x * 64;

    float4 bv = *reinterpret_cast<const float4*>(bias + f0);
    float acc[8][4];
    #pragma unroll
    for (int n = 0; n < 8; n++) {
        acc[n][0] = bv.x; acc[n][1] = bv.y; acc[n][2] = bv.z; acc[n][3] = bv.w;
    }

    for (int kt = 0; kt < FDIM; kt += 32) {
        #pragma unroll
        for (int i = tid; i < 1024; i += 256) {
            int kk = i >> 5;
            int fq = (i & 31) * 4;
            *reinterpret_cast<float4*>(&sWr[kk][fq]) =
                *reinterpret_cast<const float4*>(Wrel + (size_t)(kt + kk) * FDIM + fq);
            *reinterpret_cast<float4*>(&sWo[kk][fq]) =
                *reinterpret_cast<const float4*>(Wroot + (size_t)(kt + kk) * FDIM + fq);
        }
        #pragma unroll
        for (int i = tid; i < 512; i += 256) {
            int n  = i >> 3;
            int kq = (i & 7) * 4;
            int node = nodeBase + n;
            float4 xv = make_float4(0.f, 0.f, 0.f, 0.f);
            float4 av = xv;
            if (node < NODES) {
                xv = *reinterpret_cast<const float4*>(xin + (size_t)node * FDIM + kt + kq);
                av = *reinterpret_cast<const float4*>(agg + (size_t)node * FDIM + kt + kq);
            }
            *reinterpret_cast<float4*>(&sX[n][kq]) = xv;
            *reinterpret_cast<float4*>(&sA[n][kq]) = av;
        }
        __syncthreads();

        #pragma unroll 8
        for (int kk = 0; kk < 32; kk++) {
            float4 wr = *reinterpret_cast<const float4*>(&sWr[kk][f0]);
            float4 wo = *reinterpret_cast<const float4*>(&sWo[kk][f0]);
            #pragma unroll
            for (int n = 0; n < 8; n++) {
                float xv = sX[ty * 8 + n][kk];
                float av = sA[ty * 8 + n][kk];
                acc[n][0] = fmaf(av, wr.x, fmaf(xv, wo.x, acc[n][0]));
                acc[n][1] = fmaf(av, wr.y, fmaf(xv, wo.y, acc[n][1]));
                acc[n][2] = fmaf(av, wr.z, fmaf(xv, wo.z, acc[n][2]));
                acc[n][3] = fmaf(av, wr.w, fmaf(xv, wo.w, acc[n][3]));
            }
        }
        __syncthreads();
    }

    #pragma unroll
    for (int n = 0; n < 8; n++) {
        int node = nodeBase + ty * 8 + n;
        if (node < NODES) {
            float4 o;
            o.x = fmaxf(acc[n][0], 0.f);
            o.y = fmaxf(acc[n][1], 0.f);
            o.z = fmaxf(acc[n][2], 0.f);
            o.w = fmaxf(acc[n][3], 0.f);
            *reinterpret_cast<float4*>(out + (size_t)node * FDIM + f0) = o;
        }
    }
}

// ---------------------------------------------------------------------------
// Classifier: out = log_softmax([x1|x2] @ W_lin + b_lin)
// 4 nodes per warp-iteration; 8 FMA per 6 LDS; no lane divergence in mainloop.
// ---------------------------------------------------------------------------
__global__ void __launch_bounds__(128) cls_kernel(
    const float* __restrict__ x1, const float* __restrict__ x2,
    const float* __restrict__ Wlin, const float* __restrict__ blin,
    float* __restrict__ out, int nGroupsStride)
{
    __shared__ float sW[2 * FDIM * NCLS];   // 40KB
    __shared__ float sb[NCLS];
    __shared__ float sH[4][4][2 * FDIM];    // 16KB

    int tid = threadIdx.x;
    for (int i = tid; i < 2 * FDIM * NCLS; i += 128) sW[i] = Wlin[i];
    if (tid < NCLS) sb[tid] = blin[tid];
    __syncthreads();

    int wid  = tid >> 5;
    int lane = tid & 31;
    int l8   = lane & 7;
    float bias0 = sb[lane];
    float bias1 = sb[32 + l8];

    const int nGroups = (NODES + 3) / 4;
    for (int g = blockIdx.x * 4 + wid; g < nGroups; g += nGroupsStride) {
        int n0 = g * 4;
        #pragma unroll
        for (int j = 0; j < 4; j++) {
            int node = n0 + j; if (node >= NODES) node = NODES - 1;
            reinterpret_cast<float4*>(sH[wid][j])[lane] =
                reinterpret_cast<const float4*>(x1 + (size_t)node * FDIM)[lane];
            reinterpret_cast<float4*>(sH[wid][j])[32 + lane] =
                reinterpret_cast<const float4*>(x2 + (size_t)node * FDIM)[lane];
        }
        __syncwarp();

        float v0[4], v1[4];
        #pragma unroll
        for (int j = 0; j < 4; j++) { v0[j] = bias0; v1[j] = bias1; }

        #pragma unroll 4
        for (int k = 0; k < 2 * FDIM; k++) {
            float w0 = sW[k * NCLS + lane];
            float w1 = sW[k * NCLS + 32 + l8];
            #pragma unroll
            for (int j = 0; j < 4; j++) {
                float h = sH[wid][j][k];
                v0[j] = fmaf(h, w0, v0[j]);
                v1[j] = fmaf(h, w1, v1[j]);
            }
        }

        #pragma unroll
        for (int j = 0; j < 4; j++) {
            int node = n0 + j;
            float m = fmaxf(v0[j], v1[j]);   // v1 dup across lanes: harmless for max
            #pragma unroll
            for (int off = 16; off; off >>= 1)
                m = fmaxf(m, __shfl_xor_sync(0xffffffffu, m, off));
            float s = __expf(v0[j] - m) + ((lane < 8) ? __expf(v1[j] - m) : 0.f);
            #pragma unroll
            for (int off = 16; off; off >>= 1)
                s += __shfl_xor_sync(0xffffffffu, s, off);
            float lse = m + __logf(s);
            if (node < NODES) {
                out[(size_t)node * NCLS + lane] = v0[j] - lse;
                if (lane < 8) out[(size_t)node * NCLS + 32 + lane] = v1[j] - lse;
            }
        }
        __syncwarp();
    }
}

// ---------------------------------------------------------------------------
extern "C" void kernel_launch(void* const* d_in, const int* in_sizes, int n_in,
                              void* d_out, int out_size)
{
    const float* x      = (const float*)d_in[0];
    const int*   eidx   = (const int*)  d_in[1];
    const float* Wrel1  = (const float*)d_in[2];
    const float* b1     = (const float*)d_in[3];
    const float* Wroot1 = (const float*)d_in[4];
    const float* Wrel2  = (const float*)d_in[5];
    const float* b2     = (const float*)d_in[6];
    const float* Wroot2 = (const float*)d_in[7];
    const float* Wlin   = (const float*)d_in[8];
    const float* blin   = (const float*)d_in[9];
    float* out = (float*)d_out;

    int E = in_sizes[1] / 2;
    const int* src = eidx;
    const int* dst = eidx + E;

    float *agg, *x1, *x2;
    int *deg, *cursor, *off, *csr;
    cudaGetSymbolAddress((void**)&agg,    g_agg);
    cudaGetSymbolAddress((void**)&x1,     g_x1);
    cudaGetSymbolAddress((void**)&x2,     g_x2);
    cudaGetSymbolAddress((void**)&deg,    g_deg);
    cudaGetSymbolAddress((void**)&cursor, g_cursor);
    cudaGetSymbolAddress((void**)&off,    g_off);
    cudaGetSymbolAddress((void**)&csr,    g_csr);

    int eblocks = (E + 255) / 256;
    int gblocks = (NODES * 32 + 255) / 256;   // warp per node
    int cblocks = (NODES + 63) / 64;

    // --- CSR build (amortized over both layers) ---
    cudaMemsetAsync(deg,    0, NODES * sizeof(int), 0);
    cudaMemsetAsync(cursor, 0, NODES * sizeof(int), 0);
    hist_kernel<<<eblocks, 256>>>(dst, deg, E);
    scan_kernel<<<1, 1024>>>(deg, off, NODES);
    fill_kernel<<<eblocks, 256>>>(src, dst, off, cursor, csr, E);

    // --- Layer 1 ---
    gather_kernel<<<gblocks, 256>>>(x, off, csr, agg);
    conv_kernel<<<cblocks, 256>>>(x, agg, Wrel1, Wroot1, b1, x1);

    // --- Layer 2 ---
    gather_kernel<<<gblocks, 256>>>(x1, off, csr, agg);
    conv_kernel<<<cblocks, 256>>>(x1, agg, Wrel2, Wroot2, b2, x2);

    // --- Classifier + log_softmax ---
    int clsBlocks = 592;
    cls_kernel<<<clsBlocks, 128>>>(x1, x2, Wlin, blin, out, clsBlocks * 4);
}